// round 13
// baseline (speedup 1.0000x reference)
#include <cuda_runtime.h>
#include <cuda_fp16.h>
#include <cstdint>

// Problem dims
#define BATCH 4
#define SEQ   2048
#define EMBED 1024
#define HID   4096
#define VOCAB 32000

// ---------------------------------------------------------------------------
// PTX helpers (plain sm_103-legal: cp.async / ldmatrix / mma.sync only)
// ---------------------------------------------------------------------------
__device__ __forceinline__ uint32_t smem_u32(const void* p) {
    uint32_t a;
    asm("{ .reg .u64 t; cvta.to.shared.u64 t, %1; cvt.u32.u64 %0, t; }" : "=r"(a) : "l"(p));
    return a;
}
#define CP_ASYNC16(s, g) \
    asm volatile("cp.async.cg.shared.global [%0], [%1], 16;\n" :: "r"(s), "l"(g))
#define CP_COMMIT() asm volatile("cp.async.commit_group;\n" ::: "memory")
#define CP_WAIT1()  asm volatile("cp.async.wait_group 1;\n" ::: "memory")

__device__ __forceinline__ void ldsm4(uint32_t* r, uint32_t a) {
    asm volatile("ldmatrix.sync.aligned.m8n8.x4.shared.b16 {%0,%1,%2,%3}, [%4];"
        : "=r"(r[0]), "=r"(r[1]), "=r"(r[2]), "=r"(r[3]) : "r"(a));
}
__device__ __forceinline__ void ldsm4t(uint32_t* r, uint32_t a) {
    asm volatile("ldmatrix.sync.aligned.m8n8.x4.trans.shared.b16 {%0,%1,%2,%3}, [%4];"
        : "=r"(r[0]), "=r"(r[1]), "=r"(r[2]), "=r"(r[3]) : "r"(a));
}
__device__ __forceinline__ void mma16816(float* c, const uint32_t* a, const uint32_t* b) {
    asm volatile(
        "mma.sync.aligned.m16n8k16.row.col.f32.f16.f16.f32 "
        "{%0,%1,%2,%3}, {%4,%5,%6,%7}, {%8,%9}, {%0,%1,%2,%3};"
        : "+f"(c[0]), "+f"(c[1]), "+f"(c[2]), "+f"(c[3])
        : "r"(a[0]), "r"(a[1]), "r"(a[2]), "r"(a[3]), "r"(b[0]), "r"(b[1]));
}

// 128B-row SW128 swizzle: row r, 16B-chunk q (0..7) -> byte offset in tile
#define SWZ(r, q) ((uint32_t)((r) * 128 + ((((q) ^ ((r) & 7))) << 4)))
// 256B-row swizzle: per-128B-half SW128. c = 16B chunk (0..15)
#define SWZ256(r, c) ((uint32_t)((r) * 256 + (((c) & 8) << 4) + (((((c) & 7)) ^ ((r) & 7)) << 4)))

// fp16 hi/lo split
__device__ __forceinline__ void hsplit(float v, __half& h, __half& l) {
    h = __float2half_rn(v);
    l = __float2half_rn(v - __half2float(h));
}

// ---------------------------------------------------------------------------
// Scratch (device globals)
// ---------------------------------------------------------------------------
__device__ __half g_xhi   [BATCH * SEQ * EMBED];
__device__ __half g_xlo   [BATCH * SEQ * EMBED];
__device__ float  g_scores[BATCH * SEQ * SEQ];
__device__ __half g_whi   [BATCH * SEQ * SEQ];
__device__ __half g_atthi [BATCH * SEQ * EMBED];
__device__ __half g_hidhi [BATCH * SEQ * HID];
__device__ __half g_w1h   [EMBED * HID];              // fp16 copy of W1 [E,H]
__device__ __half g_w2h   [(size_t)HID * VOCAB];      // fp16 copy of W2 [H,V]

// ---------------------------------------------------------------------------
// Embedding gather: fp16 hi/lo
// ---------------------------------------------------------------------------
__global__ void embed_kernel(const int* __restrict__ ids, const float* __restrict__ emb,
                             __half* __restrict__ xhi, __half* __restrict__ xlo) {
    int row = blockIdx.x;
    int id  = ids[row];
    int t = threadIdx.x;
    float4 v = reinterpret_cast<const float4*>(emb + (long)id * EMBED)[t];
    __half h0, l0, h1, l1, h2, l2, h3, l3;
    hsplit(v.x, h0, l0); hsplit(v.y, h1, l1); hsplit(v.z, h2, l2); hsplit(v.w, h3, l3);
    __half2* dh = reinterpret_cast<__half2*>(xhi + (long)row * EMBED) + t * 2;
    __half2* dl = reinterpret_cast<__half2*>(xlo + (long)row * EMBED) + t * 2;
    dh[0] = __halves2half2(h0, h1); dh[1] = __halves2half2(h2, h3);
    dl[0] = __halves2half2(l0, l1); dl[1] = __halves2half2(l2, l3);
}

// ---------------------------------------------------------------------------
// Softmax rows (fp32 in) -> fp16 hi weights
// ---------------------------------------------------------------------------
__global__ __launch_bounds__(256)
void softmax_kernel(const float* __restrict__ scores, __half* __restrict__ whi) {
    __shared__ float red[256];
    const float* row = scores + (long)blockIdx.x * SEQ;
    __half* oh = whi + (long)blockIdx.x * SEQ;
    const int tid = threadIdx.x;

    float v[8];
    float lmax = -3.402823466e+38f;
    #pragma unroll
    for (int i = 0; i < 8; i++) { v[i] = row[tid + i * 256]; lmax = fmaxf(lmax, v[i]); }
    red[tid] = lmax; __syncthreads();
    #pragma unroll
    for (int s = 128; s > 0; s >>= 1) { if (tid < s) red[tid] = fmaxf(red[tid], red[tid + s]); __syncthreads(); }
    float m = red[0]; __syncthreads();

    float lsum = 0.f;
    #pragma unroll
    for (int i = 0; i < 8; i++) { v[i] = __expf(v[i] - m); lsum += v[i]; }
    red[tid] = lsum; __syncthreads();
    #pragma unroll
    for (int s = 128; s > 0; s >>= 1) { if (tid < s) red[tid] += red[tid + s]; __syncthreads(); }
    float inv = 1.f / red[0];
    #pragma unroll
    for (int i = 0; i < 8; i++)
        oh[tid + i * 256] = __float2half_rn(v[i] * inv);
}

// ---------------------------------------------------------------------------
// 3-term split-fp16 symmetric GEMM (scores) + fused weight fp32->fp16 convert.
// C = A*A^T, upper-tri tiles + mirror. CTA 128x128, BK=64, 8 warps, 3 stages.
// After GEMM work each CTA converts its linear slice of W1,W2 to fp16.
// ---------------------------------------------------------------------------
#define BMT 128
#define BKT 64
#define TILE_BYTES 16384    // 128 rows x 128 B

__device__ __forceinline__ void load_chunk_sym(uint32_t sbase, int st,
    const __half* __restrict__ gA0, const __half* __restrict__ gA1,
    const __half* __restrict__ gB0, const __half* __restrict__ gB1,
    int K, int k0, int tid)
{
    uint32_t s0 = sbase + (uint32_t)(st * 4 * TILE_BYTES);
    #pragma unroll
    for (int it = 0; it < 4; it++) {
        int idx = tid + it * 256;
        int r = idx >> 3, c = idx & 7;
        uint32_t so = SWZ(r, c);
        long go = (long)r * K + k0 + c * 8;
        CP_ASYNC16(s0 + 0 * TILE_BYTES + so, gA0 + go);
        CP_ASYNC16(s0 + 1 * TILE_BYTES + so, gA1 + go);
        CP_ASYNC16(s0 + 2 * TILE_BYTES + so, gB0 + go);
        CP_ASYNC16(s0 + 3 * TILE_BYTES + so, gB1 + go);
    }
}

__global__ __launch_bounds__(256, 1)
void hgemm_sym(const __half* __restrict__ A0, const __half* __restrict__ A1,
               float* __restrict__ Cf, int N, int K, long sA, long sC, int ntm,
               const float* __restrict__ W1, const float* __restrict__ W2,
               __half* __restrict__ w1h, __half* __restrict__ w2h)
{
    extern __shared__ char smem[];
    const uint32_t sbase = smem_u32(smem);
    const int tid  = threadIdx.x;
    const int wid  = tid >> 5, lane = tid & 31;
    const int wm   = wid & 1,  wn   = wid >> 1;

    int t0 = blockIdx.x, i0 = 0;
    while (t0 >= ntm - i0) { t0 -= ntm - i0; i0++; }
    int pm = i0, pn = i0 + t0;
    long m0 = (long)pm * BMT, n0 = (long)pn * BMT;
    long zb = blockIdx.z;
    const __half* gA0 = A0 + zb * sA + m0 * K;
    const __half* gA1 = A1 + zb * sA + m0 * K;
    const __half* gB0 = A0 + zb * sA + n0 * K;
    const __half* gB1 = A1 + zb * sA + n0 * K;

    float acc[4][4][4];
    #pragma unroll
    for (int i = 0; i < 4; i++)
        #pragma unroll
        for (int j = 0; j < 4; j++)
            #pragma unroll
            for (int k = 0; k < 4; k++) acc[i][j][k] = 0.f;

    const int ar = lane & 15;
    const int ak = (lane >> 4) << 3;
    const int br = ((lane >> 4) << 3) + (lane & 7);
    const int bk = ((lane >> 3) & 1) << 3;

    load_chunk_sym(sbase, 0, gA0, gA1, gB0, gB1, K, 0, tid);   CP_COMMIT();
    load_chunk_sym(sbase, 1, gA0, gA1, gB0, gB1, K, BKT, tid); CP_COMMIT();

    const int nc = K / BKT;
    for (int c = 0; c < nc; c++) {
        CP_WAIT1();
        __syncthreads();
        if (c + 2 < nc)
            load_chunk_sym(sbase, (c + 2) % 3, gA0, gA1, gB0, gB1, K, (c + 2) * BKT, tid);
        CP_COMMIT();

        uint32_t s0 = sbase + (uint32_t)((c % 3) * 4 * TILE_BYTES);
        #pragma unroll
        for (int kb = 0; kb < BKT; kb += 16) {
            uint32_t a0f[4][4], a1f[4][4], b0f[2][4], b1f[2][4];
            int aq = (kb + ak) >> 3;
            int bq = (kb + bk) >> 3;
            #pragma unroll
            for (int mt = 0; mt < 4; mt++) {
                int r = wm * 64 + mt * 16 + ar;
                uint32_t ad = s0 + SWZ(r, aq);
                ldsm4(a0f[mt], ad);
                ldsm4(a1f[mt], ad + TILE_BYTES);
            }
            #pragma unroll
            for (int nt = 0; nt < 2; nt++) {
                int r = wn * 32 + nt * 16 + br;
                uint32_t bd = s0 + 2 * TILE_BYTES + SWZ(r, bq);
                ldsm4(b0f[nt], bd);
                ldsm4(b1f[nt], bd + TILE_BYTES);
            }
            #pragma unroll
            for (int mt = 0; mt < 4; mt++)
                #pragma unroll
                for (int n8 = 0; n8 < 4; n8++) {
                    const uint32_t* b = &b0f[n8 >> 1][(n8 & 1) * 2];
                    mma16816(acc[mt][n8], a0f[mt], b);
                    mma16816(acc[mt][n8], a1f[mt], b);
                    mma16816(acc[mt][n8], a0f[mt], &b1f[n8 >> 1][(n8 & 1) * 2]);
                }
        }
    }

    // ---- epilogue (direct tile) ----
    long zC = zb * sC;
    int rb = lane >> 2;
    int cb = (lane & 3) * 2;
    #pragma unroll
    for (int mt = 0; mt < 4; mt++) {
        #pragma unroll
        for (int n8 = 0; n8 < 4; n8++) {
            long col = n0 + wn * 32 + n8 * 8 + cb;
            #pragma unroll
            for (int h = 0; h < 2; h++) {
                long row = m0 + wm * 64 + mt * 16 + rb + h * 8;
                *reinterpret_cast<float2*>(Cf + zC + row * (long)N + col) =
                    make_float2(acc[mt][n8][h * 2 + 0], acc[mt][n8][h * 2 + 1]);
            }
        }
    }

    // ---- mirror transposed tile at (pn, pm) ----
    if (pm != pn) {
        __syncthreads();
        float* stg = reinterpret_cast<float*>(smem);   // 128 x 129 floats
        #pragma unroll
        for (int mt = 0; mt < 4; mt++)
            #pragma unroll
            for (int n8 = 0; n8 < 4; n8++) {
                int colb = wn * 32 + n8 * 8 + cb;
                #pragma unroll
                for (int h = 0; h < 2; h++) {
                    int rowb = wm * 64 + mt * 16 + rb + h * 8;
                    stg[rowb * 129 + colb]     = acc[mt][n8][h * 2 + 0];
                    stg[rowb * 129 + colb + 1] = acc[mt][n8][h * 2 + 1];
                }
            }
        __syncthreads();
        #pragma unroll
        for (int it = 0; it < 64; it++) {
            int idx = tid + it * 256;
            int rr = idx >> 7, cc = idx & 127;
            Cf[zC + (n0 + rr) * (long)N + m0 + cc] = stg[cc * 129 + rr];
        }
    }

    // ---- fused weight conversion: this CTA's linear slice of W1 ++ W2 ----
    {
        const long W1Q  = (long)EMBED * HID / 4;                 // float4 count W1
        const long TOTQ = W1Q + (long)HID * VOCAB / 4;           // total float4
        long nCta = (long)gridDim.x * gridDim.z;                 // 544
        long cid  = zb * gridDim.x + blockIdx.x;
        long per  = (TOTQ + nCta - 1) / nCta;
        long lo = cid * per;
        long hi = lo + per; if (hi > TOTQ) hi = TOTQ;
        const float4* s1 = reinterpret_cast<const float4*>(W1);
        const float4* s2 = reinterpret_cast<const float4*>(W2);
        uint2* d1 = reinterpret_cast<uint2*>(w1h);
        uint2* d2 = reinterpret_cast<uint2*>(w2h);
        for (long i = lo + tid; i < hi; i += 256) {
            float4 v;
            if (i < W1Q) v = s1[i]; else v = s2[i - W1Q];
            __half2 p0 = __halves2half2(__float2half_rn(v.x), __float2half_rn(v.y));
            __half2 p1 = __halves2half2(__float2half_rn(v.z), __float2half_rn(v.w));
            uint2 o;
            o.x = *reinterpret_cast<uint32_t*>(&p0);
            o.y = *reinterpret_cast<uint32_t*>(&p1);
            if (i < W1Q) d1[i] = o; else d2[i - W1Q] = o;
        }
    }
}

// ---------------------------------------------------------------------------
// 1-term NN HMMA GEMM (attended, FFN1, FFN2):  C[M,N] = A[M,K] * B[K,N]
// A row-major [M,K]; B row-major [K,N] loaded with trans-ldmatrix.
// 2 CTAs/SM, CTA 128x128, BK=64, 8 warps, 3 stages (96 KB/CTA).
// OUT=0: fp32.  OUT=1: fp16 hi.  Batched via z.  B row stride = N.
// ---------------------------------------------------------------------------
#define NN_STAGE (2 * TILE_BYTES)      // A tile (16KB) + B tile (16KB)
#define NN_SMEM  (3 * NN_STAGE)        // 98304

__device__ __forceinline__ void load_chunk_nn(uint32_t sbase, int st,
    const __half* __restrict__ gA, const __half* __restrict__ gB,
    int K, int N, int k0, int tid)
{
    uint32_t s0 = sbase + (uint32_t)(st * NN_STAGE);
    // A: 128 rows x 128B (K-major)
    #pragma unroll
    for (int it = 0; it < 4; it++) {
        int idx = tid + it * 256;
        int r = idx >> 3, c = idx & 7;
        CP_ASYNC16(s0 + SWZ(r, c), gA + (long)r * K + k0 + c * 8);
    }
    // B: 64 rows x 256B (N-major rows of the [K,N] tile)
    #pragma unroll
    for (int it = 0; it < 4; it++) {
        int idx = tid + it * 256;
        int r = idx >> 4, c = idx & 15;
        CP_ASYNC16(s0 + TILE_BYTES + SWZ256(r, c), gB + (long)(k0 + r) * N + c * 8);
    }
}

template<int OUT, bool BIAS, bool RELU>
__global__ __launch_bounds__(256, 2)
void hgemm_nn(const __half* __restrict__ A0, const __half* __restrict__ B0,
              const float* __restrict__ bias,
              float* __restrict__ Cf, __half* __restrict__ Chi,
              int M, int N, int K, long sA, long sB, long sC, int ntm)
{
    extern __shared__ char smem[];
    const uint32_t sbase = smem_u32(smem);
    const int tid  = threadIdx.x;
    const int wid  = tid >> 5, lane = tid & 31;
    const int wm   = wid & 1,  wn   = wid >> 1;

    int pm = blockIdx.x % ntm, pn = blockIdx.x / ntm;
    long m0 = (long)pm * 128, n0 = (long)pn * 128;
    long zb = blockIdx.z;
    const __half* gA = A0 + zb * sA + m0 * K;
    const __half* gB = B0 + zb * sB + n0;     // [K,N] tile at column n0

    float acc[4][4][4];
    #pragma unroll
    for (int i = 0; i < 4; i++)
        #pragma unroll
        for (int j = 0; j < 4; j++)
            #pragma unroll
            for (int k = 0; k < 4; k++) acc[i][j][k] = 0.f;

    const int ar = lane & 15;
    const int ak = (lane >> 4) << 3;
    const int bkr = ((lane >> 3) & 1) << 3;   // +8 k rows for matrices 1,3
    const int bnc = lane >> 4;                // +1 n-chunk for matrices 2,3

    load_chunk_nn(sbase, 0, gA, gB, K, N, 0, tid);    CP_COMMIT();
    load_chunk_nn(sbase, 1, gA, gB, K, N, BKT, tid);  CP_COMMIT();

    const int nc = K / BKT;
    for (int c = 0; c < nc; c++) {
        CP_WAIT1();
        __syncthreads();
        if (c + 2 < nc)
            load_chunk_nn(sbase, (c + 2) % 3, gA, gB, K, N, (c + 2) * BKT, tid);
        CP_COMMIT();

        uint32_t s0 = sbase + (uint32_t)((c % 3) * NN_STAGE);
        #pragma unroll
        for (int kb = 0; kb < BKT; kb += 16) {
            uint32_t af[4][4], bf[2][4];
            int aq = (kb + ak) >> 3;
            int kr = kb + bkr + (lane & 7);
            #pragma unroll
            for (int mt = 0; mt < 4; mt++) {
                int r = wm * 64 + mt * 16 + ar;
                ldsm4(af[mt], s0 + SWZ(r, aq));
            }
            #pragma unroll
            for (int nt = 0; nt < 2; nt++) {
                int cc = wn * 4 + nt * 2 + bnc;   // 16B chunk within 256B row
                ldsm4t(bf[nt], s0 + TILE_BYTES + SWZ256(kr, cc));
            }
            #pragma unroll
            for (int mt = 0; mt < 4; mt++)
                #pragma unroll
                for (int n8 = 0; n8 < 4; n8++)
                    mma16816(acc[mt][n8], af[mt], &bf[n8 >> 1][(n8 & 1) * 2]);
        }
    }

    // ---- epilogue ----
    long zC = zb * sC;
    int rb = lane >> 2;
    int cb = (lane & 3) * 2;
    #pragma unroll
    for (int mt = 0; mt < 4; mt++) {
        #pragma unroll
        for (int n8 = 0; n8 < 4; n8++) {
            long col = n0 + wn * 32 + n8 * 8 + cb;
            float bv0 = 0.f, bv1 = 0.f;
            if (BIAS) { bv0 = bias[col]; bv1 = bias[col + 1]; }
            #pragma unroll
            for (int h = 0; h < 2; h++) {
                long row = m0 + wm * 64 + mt * 16 + rb + h * 8;
                float v0 = acc[mt][n8][h * 2 + 0] + bv0;
                float v1 = acc[mt][n8][h * 2 + 1] + bv1;
                if (RELU) { v0 = fmaxf(v0, 0.f); v1 = fmaxf(v1, 0.f); }
                long o = row * (long)N + col;
                if (OUT == 0) {
                    *reinterpret_cast<float2*>(Cf + zC + o) = make_float2(v0, v1);
                } else {
                    *reinterpret_cast<__half2*>(Chi + zC + o) =
                        __halves2half2(__float2half_rn(v0), __float2half_rn(v1));
                }
            }
        }
    }
}

// ---------------------------------------------------------------------------
// Launch
// ---------------------------------------------------------------------------
extern "C" void kernel_launch(void* const* d_in, const int* in_sizes, int n_in,
                              void* d_out, int out_size) {
    const int*   ids = (const int*)  d_in[0];
    const float* emb = (const float*)d_in[1];
    const float* W1  = (const float*)d_in[2];
    const float* b1  = (const float*)d_in[3];
    const float* W2  = (const float*)d_in[4];
    const float* b2  = (const float*)d_in[5];
    float* out = (float*)d_out;

    float* scores;
    __half *xhi, *xlo, *whi, *athi, *hdhi, *w1h, *w2h;
    cudaGetSymbolAddress((void**)&scores, g_scores);
    cudaGetSymbolAddress((void**)&xhi,    g_xhi);
    cudaGetSymbolAddress((void**)&xlo,    g_xlo);
    cudaGetSymbolAddress((void**)&whi,    g_whi);
    cudaGetSymbolAddress((void**)&athi,   g_atthi);
    cudaGetSymbolAddress((void**)&hdhi,   g_hidhi);
    cudaGetSymbolAddress((void**)&w1h,    g_w1h);
    cudaGetSymbolAddress((void**)&w2h,    g_w2h);

    const int SM3 = 4 * 3 * TILE_BYTES;   // scores: 196608
    cudaFuncSetAttribute(hgemm_sym, cudaFuncAttributeMaxDynamicSharedMemorySize, SM3);
    cudaFuncSetAttribute(hgemm_nn<1, false, false>, cudaFuncAttributeMaxDynamicSharedMemorySize, NN_SMEM);
    cudaFuncSetAttribute(hgemm_nn<1, true,  true >, cudaFuncAttributeMaxDynamicSharedMemorySize, NN_SMEM);
    cudaFuncSetAttribute(hgemm_nn<0, true,  false>, cudaFuncAttributeMaxDynamicSharedMemorySize, NN_SMEM);

    // 0) embedding -> x hi/lo fp16
    embed_kernel<<<BATCH * SEQ, 256>>>(ids, emb, xhi, xlo);

    // 1) scores = x @ x^T (3-term symmetric, upper-tri + mirror)
    //    + fused W1/W2 fp32->fp16 conversion in the CTA tails
    {
        const int ntm = SEQ / BMT;                 // 16
        dim3 grid(ntm * (ntm + 1) / 2, 1, BATCH);  // 136 x 4
        hgemm_sym<<<grid, 256, SM3>>>(
            xhi, xlo, scores, SEQ, EMBED, (long)SEQ * EMBED, (long)SEQ * SEQ, ntm,
            W1, W2, w1h, w2h);
    }

    // 2) softmax -> w hi
    softmax_kernel<<<BATCH * SEQ, 256>>>(scores, whi);

    // 3) attended = w @ x  (NN: B = xhi [S,E] row-major)  M=2048 N=1024 K=2048
    {
        dim3 grid((SEQ / 128) * (EMBED / 128), 1, BATCH);
        hgemm_nn<1, false, false><<<grid, 256, NN_SMEM>>>(
            whi, xhi, nullptr, nullptr, athi,
            SEQ, EMBED, SEQ,
            (long)SEQ * SEQ, (long)SEQ * EMBED, (long)SEQ * EMBED,
            SEQ / 128);
    }

    // 4) hidden = relu(att @ W1 + b1)  (NN: B = w1h [E,H])  M=8192 N=4096 K=1024
    {
        dim3 grid(((BATCH * SEQ) / 128) * (HID / 128), 1, 1);
        hgemm_nn<1, true, true><<<grid, 256, NN_SMEM>>>(
            athi, w1h, b1, nullptr, hdhi,
            BATCH * SEQ, HID, EMBED, 0, 0, 0,
            (BATCH * SEQ) / 128);
    }

    // 5) logits = hidden @ W2 + b2  (NN: B = w2h [H,V])  M=8192 N=32000 K=4096
    {
        dim3 grid(((BATCH * SEQ) / 128) * (VOCAB / 128), 1, 1);
        hgemm_nn<0, true, false><<<grid, 256, NN_SMEM>>>(
            hdhi, w2h, b2, out, nullptr,
            BATCH * SEQ, VOCAB, HID, 0, 0, 0,
            (BATCH * SEQ) / 128);
    }
}